// round 11
// baseline (speedup 1.0000x reference)
#include <cuda_runtime.h>
#include <cstdint>

// ---------------------------------------------------------------------------
// QuantumFeedForwardBlock: 8-wire statevector sim (1 warp/token) + MLP GEMM
// Inputs (metadata order): x[4,4096,512] f32, ry_theta[8], rand_params[20],
//                          W1[64,8], b1[64], W2[512,64], b2[512]
// Output: f32 [4,4096,512]
// ---------------------------------------------------------------------------

#define NOPS 20
#define MAXTOK 16384

__device__ float g_H[MAXTOK * 64];   // hidden activations scratch (4 MB)

struct Ops { int kind[NOPS]; int a[NOPS]; int b[NOPS]; };

// ---------------- host-side numpy-legacy MT19937 ---------------------------
namespace mtns {
struct MT { uint32_t mt[624]; int mti; };
static void mt_seed(MT& s, uint32_t seed) {
    s.mt[0] = seed;
    for (int i = 1; i < 624; i++)
        s.mt[i] = 1812433253u * (s.mt[i-1] ^ (s.mt[i-1] >> 30)) + (uint32_t)i;
    s.mti = 624;
}
static uint32_t mt_next(MT& s) {
    if (s.mti >= 624) {
        for (int i = 0; i < 624; i++) {
            uint32_t y = (s.mt[i] & 0x80000000u) | (s.mt[(i+1)%624] & 0x7fffffffu);
            uint32_t v = s.mt[(i+397)%624] ^ (y >> 1);
            if (y & 1u) v ^= 0x9908b0dfu;
            s.mt[i] = v;
        }
        s.mti = 0;
    }
    uint32_t y = s.mt[s.mti++];
    y ^= y >> 11;
    y ^= (y << 7)  & 0x9d2c5680u;
    y ^= (y << 15) & 0xefc60000u;
    y ^= y >> 18;
    return y;
}
// masked-rejection draw in [0, maxv] using 32-bit outputs (numpy legacy path
// for ranges < 2^32: randint dtype=int64 and random_interval both use this)
static uint32_t bounded(MT& s, uint32_t maxv) {
    uint32_t mask = maxv;
    mask |= mask >> 1; mask |= mask >> 2; mask |= mask >> 4;
    mask |= mask >> 8; mask |= mask >> 16;
    uint32_t v;
    do { v = mt_next(s) & mask; } while (v > maxv);
    return v;
}
} // namespace mtns

static Ops build_ops() {
    Ops ops;
    mtns::MT st;
    mtns::mt_seed(st, 0u);
    for (int i = 0; i < NOPS; i++) {
        uint32_t k = mtns::bounded(st, 3u);           // randint(4)
        if (k == 3u) {                                 // cnot: choice(8,2,False)
            int perm[8];
            for (int j = 0; j < 8; j++) perm[j] = j;
            for (int ii = 7; ii >= 1; ii--) {          // legacy shuffle (F-Y back)
                uint32_t j = mtns::bounded(st, (uint32_t)ii);
                int t = perm[ii]; perm[ii] = perm[j]; perm[j] = t;
            }
            ops.kind[i] = 3; ops.a[i] = perm[0]; ops.b[i] = perm[1];
        } else {
            uint32_t w = mtns::bounded(st, 7u);        // randint(8)
            ops.kind[i] = (int)k; ops.a[i] = (int)w; ops.b[i] = 0;
        }
    }
    return ops;
}

// ---------------- device helpers -------------------------------------------
__device__ __forceinline__ double cpack(float r, float i) {
    return __hiloint2double(__float_as_int(i), __float_as_int(r));
}
__device__ __forceinline__ void cunpack(double d, float& r, float& i) {
    r = __int_as_float(__double2loint(d));
    i = __int_as_float(__double2hiint(d));
}

// RX on a lane bit (symmetric): a' = c*a - i*s*partner
__device__ __forceinline__ void rx_lane(float (&re)[8], float (&im)[8],
                                        float c, float s, int m) {
#pragma unroll
    for (int r = 0; r < 8; r++) {
        double d = __shfl_xor_sync(0xffffffffu, cpack(re[r], im[r]), m);
        float pr, pi; cunpack(d, pr, pi);
        float nr = c * re[r] + s * pi;
        float ni = c * im[r] - s * pr;
        re[r] = nr; im[r] = ni;
    }
}
// RY on a lane bit: side 0 gets -s*partner, side 1 gets +s*partner
__device__ __forceinline__ void ry_lane(float (&re)[8], float (&im)[8],
                                        float c, float s, int m, int lane) {
    float ss = (lane & m) ? s : -s;
#pragma unroll
    for (int r = 0; r < 8; r++) {
        double d = __shfl_xor_sync(0xffffffffu, cpack(re[r], im[r]), m);
        float pr, pi; cunpack(d, pr, pi);
        re[r] = c * re[r] + ss * pr;
        im[r] = c * im[r] + ss * pi;
    }
}
// RZ: diagonal phase exp(-i*th/2*z) : bit=0 -> c - i s ; bit=1 -> c + i s
__device__ __forceinline__ void rz_any(float (&re)[8], float (&im)[8],
                                       float c, float s, int p, int base) {
#pragma unroll
    for (int r = 0; r < 8; r++) {
        float se = (((unsigned)(base | r) >> p) & 1u) ? s : -s;
        float nr = c * re[r] - se * im[r];
        float ni = c * im[r] + se * re[r];
        re[r] = nr; im[r] = ni;
    }
}
template<int TM>
__device__ __forceinline__ void rx_reg(float (&re)[8], float (&im)[8],
                                       float c, float s) {
#pragma unroll
    for (int r = 0; r < 8; r++) {
        if (r & TM) continue;
        const int q = r | TM;
        float ar = re[r], ai = im[r], br = re[q], bi = im[q];
        re[r] = c*ar + s*bi;  im[r] = c*ai - s*br;
        re[q] = c*br + s*ai;  im[q] = c*bi - s*ar;
    }
}
template<int TM>
__device__ __forceinline__ void ry_reg(float (&re)[8], float (&im)[8],
                                       float c, float s) {
#pragma unroll
    for (int r = 0; r < 8; r++) {
        if (r & TM) continue;
        const int q = r | TM;
        float ar = re[r], ai = im[r], br = re[q], bi = im[q];
        re[r] = c*ar - s*br;  im[r] = c*ai - s*bi;
        re[q] = s*ar + c*br;  im[q] = s*ai + c*bi;
    }
}
// CNOT, target bit is a register bit (TM in {1,2,4}); control bit cp runtime
template<int TM>
__device__ __forceinline__ void cnot_regT(float (&re)[8], float (&im)[8],
                                          int cp, int base) {
#pragma unroll
    for (int r = 0; r < 8; r++) {
        if (r & TM) continue;
        const int q = r | TM;
        bool cb = (((unsigned)(base | r) >> cp) & 1u) != 0u;
        float ar = re[r], ai = im[r], br = re[q], bi = im[q];
        re[r] = cb ? br : ar;  im[r] = cb ? bi : ai;
        re[q] = cb ? ar : br;  im[q] = cb ? ai : bi;
    }
}
// CNOT, target bit is a lane bit (mask m); control bit cp runtime
__device__ __forceinline__ void cnot_laneT(float (&re)[8], float (&im)[8],
                                           int m, int cp, int base) {
#pragma unroll
    for (int r = 0; r < 8; r++) {
        double d = __shfl_xor_sync(0xffffffffu, cpack(re[r], im[r]), m);
        bool cb = (((unsigned)(base | r) >> cp) & 1u) != 0u;
        float pr, pi; cunpack(d, pr, pi);
        re[r] = cb ? pr : re[r];
        im[r] = cb ? pi : im[r];
    }
}

// ---------------- kernel 1: statevector sim + MLP layer 1 ------------------
__global__ __launch_bounds__(256)
void qsim_kernel(const float* __restrict__ x,
                 const float* __restrict__ ry_theta,
                 const float* __restrict__ rand_params,
                 const float* __restrict__ W1,
                 const float* __restrict__ b1,
                 Ops ops)
{
    __shared__ float gc[28], gs[28];
    __shared__ float W1t[8 * 64];
    __shared__ float b1s[64];

    const int tid = threadIdx.x;
    if (tid < 28) {
        float th = 0.f;
        bool rot = true;
        if (tid < 20) {
            if (ops.kind[tid] == 3) rot = false;
            else th = rand_params[tid];
        } else {
            th = ry_theta[tid - 20];
        }
        float s, c;
        sincosf(0.5f * th, &s, &c);
        gc[tid] = rot ? c : 1.f;
        gs[tid] = rot ? s : 0.f;
    }
    if (tid < 64) b1s[tid] = b1[tid];
    for (int i = tid; i < 512; i += 256) {
        int j = i >> 3, w = i & 7;
        W1t[w * 64 + j] = W1[i];          // transpose: conflict-free reads
    }
    __syncthreads();

    const int lane  = tid & 31;
    const int wid   = tid >> 5;
    const int token = blockIdx.x * 8 + wid;
    const int base  = lane << 3;          // global amp index = base | r

    // ---- initial product state from the 8 input features ----
    const float* xf = x + (size_t)token * 512;
    float cw[8], sw[8];
#pragma unroll
    for (int w = 0; w < 8; w++) {
        float f = __ldg(xf + w);
        __sincosf(0.5f * f, &sw[w], &cw[w]);
    }
    float lf = 1.f;
#pragma unroll
    for (int w = 0; w < 5; w++)           // wires 0..4 live on lane bits 4..0
        lf *= ((lane >> (4 - w)) & 1) ? sw[w] : cw[w];
    float re[8], im[8];
#pragma unroll
    for (int r = 0; r < 8; r++) {
        float v = lf;
        v *= (r & 4) ? sw[5] : cw[5];
        v *= (r & 2) ? sw[6] : cw[6];
        v *= (r & 1) ? sw[7] : cw[7];
        re[r] = v; im[r] = 0.f;
    }

    // ---- 20 random gates + 8 final RY gates ----
#pragma unroll 1
    for (int g = 0; g < 28; g++) {
        int kind, w;
        if (g < 20) { kind = ops.kind[g]; w = ops.a[g]; }
        else        { kind = 1;           w = g - 20;   }
        const float c = gc[g], s = gs[g];
        if (kind == 3) {
            const int cp = 7 - ops.a[g];
            const int tp = 7 - ops.b[g];
            if (tp >= 3)      cnot_laneT(re, im, 1 << (tp - 3), cp, base);
            else if (tp == 2) cnot_regT<4>(re, im, cp, base);
            else if (tp == 1) cnot_regT<2>(re, im, cp, base);
            else              cnot_regT<1>(re, im, cp, base);
        } else {
            const int p = 7 - w;
            if (kind == 2) {
                rz_any(re, im, c, s, p, base);
            } else if (kind == 0) {       // rx
                if (p >= 3)      rx_lane(re, im, c, s, 1 << (p - 3));
                else if (p == 2) rx_reg<4>(re, im, c, s);
                else if (p == 1) rx_reg<2>(re, im, c, s);
                else             rx_reg<1>(re, im, c, s);
            } else {                      // ry
                if (p >= 3)      ry_lane(re, im, c, s, 1 << (p - 3), lane);
                else if (p == 2) ry_reg<4>(re, im, c, s);
                else if (p == 1) ry_reg<2>(re, im, c, s);
                else             ry_reg<1>(re, im, c, s);
            }
        }
    }

    // ---- probs -> 8 Z expectations (butterfly reductions) ----
    float S = 0.f, E5 = 0.f, E6 = 0.f, E7 = 0.f;
#pragma unroll
    for (int r = 0; r < 8; r++) {
        float p = re[r] * re[r] + im[r] * im[r];
        S  += p;
        E5 += (r & 4) ? -p : p;           // wire 5 <-> amp bit 2
        E6 += (r & 2) ? -p : p;           // wire 6 <-> amp bit 1
        E7 += (r & 1) ? -p : p;           // wire 7 <-> amp bit 0
    }
    float ev[8];
#pragma unroll
    for (int w = 0; w < 5; w++) {         // wire w <-> lane bit (4-w)
        float v = ((lane >> (4 - w)) & 1) ? -S : S;
#pragma unroll
        for (int m = 16; m >= 1; m >>= 1) v += __shfl_xor_sync(0xffffffffu, v, m);
        ev[w] = v;
    }
    {
        float Ein[3] = {E5, E6, E7};
#pragma unroll
        for (int w = 5; w < 8; w++) {
            float v = Ein[w - 5];
#pragma unroll
            for (int m = 16; m >= 1; m >>= 1) v += __shfl_xor_sync(0xffffffffu, v, m);
            ev[w] = v;
        }
    }

    // ---- MLP layer 1: h = relu(ev @ W1^T + b1), 2 outputs per lane ----
    float* Hrow = g_H + (size_t)token * 64;
#pragma unroll
    for (int half = 0; half < 2; half++) {
        const int j = lane + half * 32;
        float acc = b1s[j];
#pragma unroll
        for (int w = 0; w < 8; w++) acc = fmaf(ev[w], W1t[w * 64 + j], acc);
        Hrow[j] = fmaxf(acc, 0.f);
    }
}

// ---------------- kernel 2: out = H @ W2^T + b2 ----------------------------
// M=tokens, N=512, K=64.  64x64 tile per 256-thread block, 4x4 micro-tile.
__global__ __launch_bounds__(256)
void mlp2_kernel(const float* __restrict__ W2,
                 const float* __restrict__ b2,
                 float* __restrict__ out)
{
    __shared__ float As[64][68];   // As[k][m]  (stride 68: 16B-aligned rows)
    __shared__ float Bs[64][68];   // Bs[k][n]

    const int tid = threadIdx.x;
    const int m0 = blockIdx.y * 64;
    const int n0 = blockIdx.x * 64;

    {
        const int row = tid >> 4;            // 0..15
        const int k0  = (tid & 15) * 4;
#pragma unroll
        for (int it = 0; it < 4; it++) {
            const int m = row + it * 16;
            float4 v = *(const float4*)(g_H + (size_t)(m0 + m) * 64 + k0);
            As[k0 + 0][m] = v.x; As[k0 + 1][m] = v.y;
            As[k0 + 2][m] = v.z; As[k0 + 3][m] = v.w;
        }
#pragma unroll
        for (int it = 0; it < 4; it++) {
            const int n = row + it * 16;
            float4 v = *(const float4*)(W2 + (size_t)(n0 + n) * 64 + k0);
            Bs[k0 + 0][n] = v.x; Bs[k0 + 1][n] = v.y;
            Bs[k0 + 2][n] = v.z; Bs[k0 + 3][n] = v.w;
        }
    }
    __syncthreads();

    const int tx = tid & 15;     // n direction, 4 cols
    const int ty = tid >> 4;     // m direction, 4 rows
    float acc[4][4];
#pragma unroll
    for (int i = 0; i < 4; i++)
#pragma unroll
        for (int j = 0; j < 4; j++) acc[i][j] = 0.f;

#pragma unroll 16
    for (int k = 0; k < 64; k++) {
        float4 a = *(const float4*)&As[k][ty * 4];
        float4 b = *(const float4*)&Bs[k][tx * 4];
        float av[4] = {a.x, a.y, a.z, a.w};
        float bv[4] = {b.x, b.y, b.z, b.w};
#pragma unroll
        for (int i = 0; i < 4; i++)
#pragma unroll
            for (int j = 0; j < 4; j++)
                acc[i][j] = fmaf(av[i], bv[j], acc[i][j]);
    }

    const float4 bb = *(const float4*)(b2 + n0 + tx * 4);
#pragma unroll
    for (int i = 0; i < 4; i++) {
        const int m = m0 + ty * 4 + i;
        float4 o;
        o.x = acc[i][0] + bb.x;
        o.y = acc[i][1] + bb.y;
        o.z = acc[i][2] + bb.z;
        o.w = acc[i][3] + bb.w;
        *(float4*)(out + (size_t)m * 512 + n0 + tx * 4) = o;
    }
}

// ---------------- entry point ----------------------------------------------
extern "C" void kernel_launch(void* const* d_in, const int* in_sizes, int n_in,
                              void* d_out, int out_size)
{
    const float* x  = (const float*)d_in[0];
    const float* ry = (const float*)d_in[1];
    const float* rp = (const float*)d_in[2];
    const float* W1 = (const float*)d_in[3];
    const float* b1 = (const float*)d_in[4];
    const float* W2 = (const float*)d_in[5];
    const float* b2 = (const float*)d_in[6];
    float* out = (float*)d_out;

    const int tokens = in_sizes[0] / 512;      // 16384

    Ops ops = build_ops();                      // deterministic, host-side

    qsim_kernel<<<tokens / 8, 256>>>(x, ry, rp, W1, b1, ops);

    dim3 g2(512 / 64, tokens / 64);
    mlp2_kernel<<<g2, 256>>>(W2, b2, out);
}

// round 12
// speedup vs baseline: 1.2101x; 1.2101x over previous
#include <cuda_runtime.h>
#include <cstdint>

// ---------------------------------------------------------------------------
// QuantumFeedForwardBlock: 8-wire statevector sim (1 warp/token) + MLP GEMM
// Inputs (metadata order): x[4,4096,512] f32, ry_theta[8], rand_params[20],
//                          W1[64,8], b1[64], W2[512,64], b2[512]
// Output: f32 [4,4096,512]
// R11: mlp2 rewritten — 128x64 tile, m-pair packed accumulators via
//      fma.rn.f32x2, H stored transposed (g_Ht[64][tokens]) by qsim.
// ---------------------------------------------------------------------------

#define NOPS 20
#define MAXTOK 16384

__device__ float g_Ht[64 * MAXTOK];   // hidden activations, TRANSPOSED [k][m]

struct Ops { int kind[NOPS]; int a[NOPS]; int b[NOPS]; };

// ---------------- host-side numpy-legacy MT19937 ---------------------------
namespace mtns {
struct MT { uint32_t mt[624]; int mti; };
static void mt_seed(MT& s, uint32_t seed) {
    s.mt[0] = seed;
    for (int i = 1; i < 624; i++)
        s.mt[i] = 1812433253u * (s.mt[i-1] ^ (s.mt[i-1] >> 30)) + (uint32_t)i;
    s.mti = 624;
}
static uint32_t mt_next(MT& s) {
    if (s.mti >= 624) {
        for (int i = 0; i < 624; i++) {
            uint32_t y = (s.mt[i] & 0x80000000u) | (s.mt[(i+1)%624] & 0x7fffffffu);
            uint32_t v = s.mt[(i+397)%624] ^ (y >> 1);
            if (y & 1u) v ^= 0x9908b0dfu;
            s.mt[i] = v;
        }
        s.mti = 0;
    }
    uint32_t y = s.mt[s.mti++];
    y ^= y >> 11;
    y ^= (y << 7)  & 0x9d2c5680u;
    y ^= (y << 15) & 0xefc60000u;
    y ^= y >> 18;
    return y;
}
static uint32_t bounded(MT& s, uint32_t maxv) {
    uint32_t mask = maxv;
    mask |= mask >> 1; mask |= mask >> 2; mask |= mask >> 4;
    mask |= mask >> 8; mask |= mask >> 16;
    uint32_t v;
    do { v = mt_next(s) & mask; } while (v > maxv);
    return v;
}
} // namespace mtns

static Ops build_ops() {
    Ops ops;
    mtns::MT st;
    mtns::mt_seed(st, 0u);
    for (int i = 0; i < NOPS; i++) {
        uint32_t k = mtns::bounded(st, 3u);           // randint(4)
        if (k == 3u) {                                 // cnot: choice(8,2,False)
            int perm[8];
            for (int j = 0; j < 8; j++) perm[j] = j;
            for (int ii = 7; ii >= 1; ii--) {          // legacy Fisher-Yates
                uint32_t j = mtns::bounded(st, (uint32_t)ii);
                int t = perm[ii]; perm[ii] = perm[j]; perm[j] = t;
            }
            ops.kind[i] = 3; ops.a[i] = perm[0]; ops.b[i] = perm[1];
        } else {
            uint32_t w = mtns::bounded(st, 7u);        // randint(8)
            ops.kind[i] = (int)k; ops.a[i] = (int)w; ops.b[i] = 0;
        }
    }
    return ops;
}

// ---------------- device helpers -------------------------------------------
__device__ __forceinline__ double cpack(float r, float i) {
    return __hiloint2double(__float_as_int(i), __float_as_int(r));
}
__device__ __forceinline__ void cunpack(double d, float& r, float& i) {
    r = __int_as_float(__double2loint(d));
    i = __int_as_float(__double2hiint(d));
}

// packed f32x2 helpers (ptxas never auto-fuses these)
__device__ __forceinline__ unsigned long long pk2(float lo, float hi) {
    unsigned long long r;
    asm("mov.b64 %0, {%1, %2};" : "=l"(r) : "f"(lo), "f"(hi));
    return r;
}
__device__ __forceinline__ void unpk2(unsigned long long v, float& lo, float& hi) {
    asm("mov.b64 {%0, %1}, %2;" : "=f"(lo), "=f"(hi) : "l"(v));
}
__device__ __forceinline__ void fma2(unsigned long long& d,
                                     unsigned long long a, unsigned long long b) {
    asm("fma.rn.f32x2 %0, %1, %2, %0;" : "+l"(d) : "l"(a), "l"(b));
}

// RX on a lane bit (symmetric): a' = c*a - i*s*partner
__device__ __forceinline__ void rx_lane(float (&re)[8], float (&im)[8],
                                        float c, float s, int m) {
#pragma unroll
    for (int r = 0; r < 8; r++) {
        double d = __shfl_xor_sync(0xffffffffu, cpack(re[r], im[r]), m);
        float pr, pi; cunpack(d, pr, pi);
        float nr = c * re[r] + s * pi;
        float ni = c * im[r] - s * pr;
        re[r] = nr; im[r] = ni;
    }
}
// RY on a lane bit
__device__ __forceinline__ void ry_lane(float (&re)[8], float (&im)[8],
                                        float c, float s, int m, int lane) {
    float ss = (lane & m) ? s : -s;
#pragma unroll
    for (int r = 0; r < 8; r++) {
        double d = __shfl_xor_sync(0xffffffffu, cpack(re[r], im[r]), m);
        float pr, pi; cunpack(d, pr, pi);
        re[r] = c * re[r] + ss * pr;
        im[r] = c * im[r] + ss * pi;
    }
}
// RZ: diagonal phase
__device__ __forceinline__ void rz_any(float (&re)[8], float (&im)[8],
                                       float c, float s, int p, int base) {
#pragma unroll
    for (int r = 0; r < 8; r++) {
        float se = (((unsigned)(base | r) >> p) & 1u) ? s : -s;
        float nr = c * re[r] - se * im[r];
        float ni = c * im[r] + se * re[r];
        re[r] = nr; im[r] = ni;
    }
}
template<int TM>
__device__ __forceinline__ void rx_reg(float (&re)[8], float (&im)[8],
                                       float c, float s) {
#pragma unroll
    for (int r = 0; r < 8; r++) {
        if (r & TM) continue;
        const int q = r | TM;
        float ar = re[r], ai = im[r], br = re[q], bi = im[q];
        re[r] = c*ar + s*bi;  im[r] = c*ai - s*br;
        re[q] = c*br + s*ai;  im[q] = c*bi - s*ar;
    }
}
template<int TM>
__device__ __forceinline__ void ry_reg(float (&re)[8], float (&im)[8],
                                       float c, float s) {
#pragma unroll
    for (int r = 0; r < 8; r++) {
        if (r & TM) continue;
        const int q = r | TM;
        float ar = re[r], ai = im[r], br = re[q], bi = im[q];
        re[r] = c*ar - s*br;  im[r] = c*ai - s*bi;
        re[q] = s*ar + c*br;  im[q] = s*ai + c*bi;
    }
}
template<int TM>
__device__ __forceinline__ void cnot_regT(float (&re)[8], float (&im)[8],
                                          int cp, int base) {
#pragma unroll
    for (int r = 0; r < 8; r++) {
        if (r & TM) continue;
        const int q = r | TM;
        bool cb = (((unsigned)(base | r) >> cp) & 1u) != 0u;
        float ar = re[r], ai = im[r], br = re[q], bi = im[q];
        re[r] = cb ? br : ar;  im[r] = cb ? bi : ai;
        re[q] = cb ? ar : br;  im[q] = cb ? ai : bi;
    }
}
__device__ __forceinline__ void cnot_laneT(float (&re)[8], float (&im)[8],
                                           int m, int cp, int base) {
#pragma unroll
    for (int r = 0; r < 8; r++) {
        double d = __shfl_xor_sync(0xffffffffu, cpack(re[r], im[r]), m);
        bool cb = (((unsigned)(base | r) >> cp) & 1u) != 0u;
        float pr, pi; cunpack(d, pr, pi);
        re[r] = cb ? pr : re[r];
        im[r] = cb ? pi : im[r];
    }
}

// ---------------- kernel 1: statevector sim + MLP layer 1 ------------------
__global__ __launch_bounds__(256)
void qsim_kernel(const float* __restrict__ x,
                 const float* __restrict__ ry_theta,
                 const float* __restrict__ rand_params,
                 const float* __restrict__ W1,
                 const float* __restrict__ b1,
                 Ops ops)
{
    __shared__ float gc[28], gs[28];
    __shared__ float W1t[8 * 64];
    __shared__ float b1s[64];
    __shared__ float Hs[64][9];           // pad 9: conflict-free scatter

    const int tid = threadIdx.x;
    if (tid < 28) {
        float th = 0.f;
        bool rot = true;
        if (tid < 20) {
            if (ops.kind[tid] == 3) rot = false;
            else th = rand_params[tid];
        } else {
            th = ry_theta[tid - 20];
        }
        float s, c;
        sincosf(0.5f * th, &s, &c);
        gc[tid] = rot ? c : 1.f;
        gs[tid] = rot ? s : 0.f;
    }
    if (tid < 64) b1s[tid] = b1[tid];
    for (int i = tid; i < 512; i += 256) {
        int j = i >> 3, w = i & 7;
        W1t[w * 64 + j] = W1[i];          // transpose: conflict-free reads
    }
    __syncthreads();

    const int lane  = tid & 31;
    const int wid   = tid >> 5;
    const int token0 = blockIdx.x * 8;
    const int token  = token0 + wid;
    const int base  = lane << 3;          // global amp index = base | r

    // ---- initial product state from the 8 input features ----
    const float* xf = x + (size_t)token * 512;
    float cw[8], sw[8];
#pragma unroll
    for (int w = 0; w < 8; w++) {
        float f = __ldg(xf + w);
        __sincosf(0.5f * f, &sw[w], &cw[w]);
    }
    float lf = 1.f;
#pragma unroll
    for (int w = 0; w < 5; w++)           // wires 0..4 live on lane bits 4..0
        lf *= ((lane >> (4 - w)) & 1) ? sw[w] : cw[w];
    float re[8], im[8];
#pragma unroll
    for (int r = 0; r < 8; r++) {
        float v = lf;
        v *= (r & 4) ? sw[5] : cw[5];
        v *= (r & 2) ? sw[6] : cw[6];
        v *= (r & 1) ? sw[7] : cw[7];
        re[r] = v; im[r] = 0.f;
    }

    // ---- 20 random gates + 8 final RY gates ----
#pragma unroll 1
    for (int g = 0; g < 28; g++) {
        int kind, w;
        if (g < 20) { kind = ops.kind[g]; w = ops.a[g]; }
        else        { kind = 1;           w = g - 20;   }
        const float c = gc[g], s = gs[g];
        if (kind == 3) {
            const int cp = 7 - ops.a[g];
            const int tp = 7 - ops.b[g];
            if (tp >= 3)      cnot_laneT(re, im, 1 << (tp - 3), cp, base);
            else if (tp == 2) cnot_regT<4>(re, im, cp, base);
            else if (tp == 1) cnot_regT<2>(re, im, cp, base);
            else              cnot_regT<1>(re, im, cp, base);
        } else {
            const int p = 7 - w;
            if (kind == 2) {
                rz_any(re, im, c, s, p, base);
            } else if (kind == 0) {       // rx
                if (p >= 3)      rx_lane(re, im, c, s, 1 << (p - 3));
                else if (p == 2) rx_reg<4>(re, im, c, s);
                else if (p == 1) rx_reg<2>(re, im, c, s);
                else             rx_reg<1>(re, im, c, s);
            } else {                      // ry
                if (p >= 3)      ry_lane(re, im, c, s, 1 << (p - 3), lane);
                else if (p == 2) ry_reg<4>(re, im, c, s);
                else if (p == 1) ry_reg<2>(re, im, c, s);
                else             ry_reg<1>(re, im, c, s);
            }
        }
    }

    // ---- probs -> 8 Z expectations (butterfly reductions) ----
    float S = 0.f, E5 = 0.f, E6 = 0.f, E7 = 0.f;
#pragma unroll
    for (int r = 0; r < 8; r++) {
        float p = re[r] * re[r] + im[r] * im[r];
        S  += p;
        E5 += (r & 4) ? -p : p;
        E6 += (r & 2) ? -p : p;
        E7 += (r & 1) ? -p : p;
    }
    float ev[8];
#pragma unroll
    for (int w = 0; w < 5; w++) {
        float v = ((lane >> (4 - w)) & 1) ? -S : S;
#pragma unroll
        for (int m = 16; m >= 1; m >>= 1) v += __shfl_xor_sync(0xffffffffu, v, m);
        ev[w] = v;
    }
    {
        float Ein[3] = {E5, E6, E7};
#pragma unroll
        for (int w = 5; w < 8; w++) {
            float v = Ein[w - 5];
#pragma unroll
            for (int m = 16; m >= 1; m >>= 1) v += __shfl_xor_sync(0xffffffffu, v, m);
            ev[w] = v;
        }
    }

    // ---- MLP layer 1: h = relu(ev @ W1^T + b1), staged to smem ----
#pragma unroll
    for (int half = 0; half < 2; half++) {
        const int j = lane + half * 32;
        float acc = b1s[j];
#pragma unroll
        for (int w = 0; w < 8; w++) acc = fmaf(ev[w], W1t[w * 64 + j], acc);
        Hs[j][wid] = fmaxf(acc, 0.f);
    }
    __syncthreads();

    // coalesced transposed writeout: g_Ht[j][token0+tok]
#pragma unroll
    for (int it = 0; it < 2; it++) {
        const int idx = it * 256 + tid;
        const int j = idx >> 3, tok = idx & 7;
        g_Ht[j * MAXTOK + token0 + tok] = Hs[j][tok];
    }
}

// ---------------- kernel 2: out = H @ W2^T + b2 ----------------------------
// M=16384, N=512, K=64.  BM=128, BN=64, 256 threads.
// Per thread: 8 m-rows x 4 n-cols, accumulators packed as m-pairs (f32x2).
__global__ __launch_bounds__(256)
void mlp2_kernel(const float* __restrict__ W2,
                 const float* __restrict__ b2,
                 float* __restrict__ out)
{
    __shared__ float As[64][128];   // As[k][m]  (from g_Ht, coalesced)
    __shared__ float Bs[64][64];    // Bs[k][n]  (W2 transposed on the fly)

    const int tid = threadIdx.x;
    const int m0 = blockIdx.y * 128;
    const int n0 = blockIdx.x * 64;

    // load A tile: 64k x 128m = 2048 float4 chunks
#pragma unroll
    for (int it = 0; it < 8; it++) {
        const int c  = it * 256 + tid;
        const int k  = c >> 5;
        const int mq = c & 31;
        float4 v = *(const float4*)(g_Ht + (size_t)k * MAXTOK + m0 + mq * 4);
        *(float4*)&As[k][mq * 4] = v;
    }
    // load B tile: W2[n0+n][kq*4..] -> Bs[k][n]; lane-major n => conflict-free
#pragma unroll
    for (int it = 0; it < 4; it++) {
        const int c  = it * 256 + tid;
        const int n  = c & 63;
        const int kq = c >> 6;
        float4 v = *(const float4*)(W2 + (size_t)(n0 + n) * 64 + kq * 4);
        Bs[kq * 4 + 0][n] = v.x;
        Bs[kq * 4 + 1][n] = v.y;
        Bs[kq * 4 + 2][n] = v.z;
        Bs[kq * 4 + 3][n] = v.w;
    }
    __syncthreads();

    const int tx = tid & 15;     // n: 4 cols at n0 + tx*4
    const int ty = tid >> 4;     // m: rows ty*4..+3 and 64+ty*4..+3

    unsigned long long acc[4][4];  // [m-pair][n], each = (out[m_lo], out[m_hi])
#pragma unroll
    for (int p = 0; p < 4; p++)
#pragma unroll
        for (int n = 0; n < 4; n++) acc[p][n] = 0ull;

#pragma unroll 16
    for (int k = 0; k < 64; k++) {
        // A as natural m-pairs: 2 x LDS.128 -> 4 packed doubles
        ulonglong2 a01 = *(const ulonglong2*)&As[k][ty * 4];
        ulonglong2 a23 = *(const ulonglong2*)&As[k][64 + ty * 4];
        unsigned long long ap[4] = {a01.x, a01.y, a23.x, a23.y};
        // B broadcast-packed: 1 x LDS.128 + 4 replicate packs
        float4 bv = *(const float4*)&Bs[k][tx * 4];
        unsigned long long bp[4] = {pk2(bv.x, bv.x), pk2(bv.y, bv.y),
                                    pk2(bv.z, bv.z), pk2(bv.w, bv.w)};
#pragma unroll
        for (int p = 0; p < 4; p++)
#pragma unroll
            for (int n = 0; n < 4; n++) fma2(acc[p][n], ap[p], bp[n]);
    }

    const float4 bb = *(const float4*)(b2 + n0 + tx * 4);
    const float bias[4] = {bb.x, bb.y, bb.z, bb.w};
#pragma unroll
    for (int p = 0; p < 4; p++) {
        // m-pair p covers rows: base + 2*(p&1)*... see mapping below
        const int rlo = m0 + ((p & 2) ? 64 : 0) + ty * 4 + (p & 1) * 2;
        float4 olo, ohi;
        float l0, h0, l1, h1, l2, h2, l3, h3;
        unpk2(acc[p][0], l0, h0);
        unpk2(acc[p][1], l1, h1);
        unpk2(acc[p][2], l2, h2);
        unpk2(acc[p][3], l3, h3);
        olo.x = l0 + bias[0]; olo.y = l1 + bias[1];
        olo.z = l2 + bias[2]; olo.w = l3 + bias[3];
        ohi.x = h0 + bias[0]; ohi.y = h1 + bias[1];
        ohi.z = h2 + bias[2]; ohi.w = h3 + bias[3];
        *(float4*)(out + (size_t)rlo * 512 + n0 + tx * 4) = olo;
        *(float4*)(out + (size_t)(rlo + 1) * 512 + n0 + tx * 4) = ohi;
    }
}

// ---------------- entry point ----------------------------------------------
extern "C" void kernel_launch(void* const* d_in, const int* in_sizes, int n_in,
                              void* d_out, int out_size)
{
    const float* x  = (const float*)d_in[0];
    const float* ry = (const float*)d_in[1];
    const float* rp = (const float*)d_in[2];
    const float* W1 = (const float*)d_in[3];
    const float* b1 = (const float*)d_in[4];
    const float* W2 = (const float*)d_in[5];
    const float* b2 = (const float*)d_in[6];
    float* out = (float*)d_out;

    const int tokens = in_sizes[0] / 512;      // 16384

    Ops ops = build_ops();                      // deterministic, host-side

    qsim_kernel<<<tokens / 8, 256>>>(x, ry, rp, W1, b1, ops);

    dim3 g2(512 / 64, tokens / 128);
    mlp2_kernel<<<g2, 256>>>(W2, b2, out);
}

// round 13
// speedup vs baseline: 1.3253x; 1.0952x over previous
#include <cuda_runtime.h>
#include <cstdint>

// ---------------------------------------------------------------------------
// QuantumFeedForwardBlock: 8-wire statevector sim (1 warp/token) + MLP GEMM
// Inputs (metadata order): x[4,4096,512] f32, ry_theta[8], rand_params[20],
//                          W1[64,8], b1[64], W2[512,64], b2[512]
// Output: f32 [4,4096,512]
// R12: gate sequence baked at COMPILE TIME (constexpr MT19937 + template
//      unroll, zero dispatch branches); mlp2 uses pre-duplicated f32x2 B
//      pairs in dynamic smem (no pk2 MOVs, conflict-free pair reads).
// ---------------------------------------------------------------------------

#define NOPS 20
#define MAXTOK 16384

__device__ float g_Ht[64 * MAXTOK];   // hidden activations, TRANSPOSED [k][m]

struct Ops { int kind[NOPS]; int a[NOPS]; int b[NOPS]; };

// ---------------- constexpr numpy-legacy MT19937 ---------------------------
struct MTState { uint32_t mt[624]; int mti; };

__host__ __device__ constexpr void mt_seed(MTState& s, uint32_t seed) {
    s.mt[0] = seed;
    for (int i = 1; i < 624; i++)
        s.mt[i] = 1812433253u * (s.mt[i-1] ^ (s.mt[i-1] >> 30)) + (uint32_t)i;
    s.mti = 624;
}
__host__ __device__ constexpr uint32_t mt_next(MTState& s) {
    if (s.mti >= 624) {
        for (int i = 0; i < 624; i++) {
            uint32_t y = (s.mt[i] & 0x80000000u) | (s.mt[(i+1)%624] & 0x7fffffffu);
            uint32_t v = s.mt[(i+397)%624] ^ (y >> 1);
            if (y & 1u) v ^= 0x9908b0dfu;
            s.mt[i] = v;
        }
        s.mti = 0;
    }
    uint32_t y = s.mt[s.mti++];
    y ^= y >> 11;
    y ^= (y << 7)  & 0x9d2c5680u;
    y ^= (y << 15) & 0xefc60000u;
    y ^= y >> 18;
    return y;
}
__host__ __device__ constexpr uint32_t mt_bounded(MTState& s, uint32_t maxv) {
    uint32_t mask = maxv;
    mask |= mask >> 1; mask |= mask >> 2; mask |= mask >> 4;
    mask |= mask >> 8; mask |= mask >> 16;
    uint32_t v = mt_next(s) & mask;
    while (v > maxv) v = mt_next(s) & mask;
    return v;
}
__host__ __device__ constexpr Ops build_ops_ce() {
    Ops ops{};
    MTState st{};
    mt_seed(st, 0u);
    for (int i = 0; i < NOPS; i++) {
        uint32_t k = mt_bounded(st, 3u);               // randint(4)
        if (k == 3u) {                                  // cnot: choice(8,2,False)
            int perm[8] = {0,1,2,3,4,5,6,7};
            for (int ii = 7; ii >= 1; ii--) {           // legacy Fisher-Yates
                uint32_t j = mt_bounded(st, (uint32_t)ii);
                int t = perm[ii]; perm[ii] = perm[j]; perm[j] = t;
            }
            ops.kind[i] = 3; ops.a[i] = perm[0]; ops.b[i] = perm[1];
        } else {
            uint32_t w = mt_bounded(st, 7u);            // randint(8)
            ops.kind[i] = (int)k; ops.a[i] = (int)w; ops.b[i] = 0;
        }
    }
    return ops;
}
__host__ __device__ constexpr int op_kind(int g) { return build_ops_ce().kind[g]; }
__host__ __device__ constexpr int op_a(int g)    { return build_ops_ce().a[g]; }
__host__ __device__ constexpr int op_b(int g)    { return build_ops_ce().b[g]; }

// ---------------- device helpers -------------------------------------------
__device__ __forceinline__ double cpack(float r, float i) {
    return __hiloint2double(__float_as_int(i), __float_as_int(r));
}
__device__ __forceinline__ void cunpack(double d, float& r, float& i) {
    r = __int_as_float(__double2loint(d));
    i = __int_as_float(__double2hiint(d));
}
__device__ __forceinline__ unsigned long long pk2(float lo, float hi) {
    unsigned long long r;
    asm("mov.b64 %0, {%1, %2};" : "=l"(r) : "f"(lo), "f"(hi));
    return r;
}
__device__ __forceinline__ void unpk2(unsigned long long v, float& lo, float& hi) {
    asm("mov.b64 {%0, %1}, %2;" : "=f"(lo), "=f"(hi) : "l"(v));
}
__device__ __forceinline__ void fma2(unsigned long long& d,
                                     unsigned long long a, unsigned long long b) {
    asm("fma.rn.f32x2 %0, %1, %2, %0;" : "+l"(d) : "l"(a), "l"(b));
}

// ---- gate helpers, masks/positions as template parameters -----------------
template<int M>
__device__ __forceinline__ void rx_lane(float (&re)[8], float (&im)[8],
                                        float c, float s) {
#pragma unroll
    for (int r = 0; r < 8; r++) {
        double d = __shfl_xor_sync(0xffffffffu, cpack(re[r], im[r]), M);
        float pr, pi; cunpack(d, pr, pi);
        float nr = c * re[r] + s * pi;
        float ni = c * im[r] - s * pr;
        re[r] = nr; im[r] = ni;
    }
}
template<int M>
__device__ __forceinline__ void ry_lane(float (&re)[8], float (&im)[8],
                                        float c, float s, int lane) {
    float ss = (lane & M) ? s : -s;
#pragma unroll
    for (int r = 0; r < 8; r++) {
        double d = __shfl_xor_sync(0xffffffffu, cpack(re[r], im[r]), M);
        float pr, pi; cunpack(d, pr, pi);
        re[r] = c * re[r] + ss * pr;
        im[r] = c * im[r] + ss * pi;
    }
}
template<int P>
__device__ __forceinline__ void rz_g(float (&re)[8], float (&im)[8],
                                     float c, float s, int lane) {
    if constexpr (P >= 3) {
        float se = ((lane >> (P - 3)) & 1) ? s : -s;
#pragma unroll
        for (int r = 0; r < 8; r++) {
            float nr = c * re[r] - se * im[r];
            float ni = c * im[r] + se * re[r];
            re[r] = nr; im[r] = ni;
        }
    } else {
#pragma unroll
        for (int r = 0; r < 8; r++) {
            const float se = ((r >> P) & 1) ? s : -s;   // compile-time sign
            float nr = c * re[r] - se * im[r];
            float ni = c * im[r] + se * re[r];
            re[r] = nr; im[r] = ni;
        }
    }
}
template<int TM>
__device__ __forceinline__ void rx_reg(float (&re)[8], float (&im)[8],
                                       float c, float s) {
#pragma unroll
    for (int r = 0; r < 8; r++) {
        if (r & TM) continue;
        const int q = r | TM;
        float ar = re[r], ai = im[r], br = re[q], bi = im[q];
        re[r] = c*ar + s*bi;  im[r] = c*ai - s*br;
        re[q] = c*br + s*ai;  im[q] = c*bi - s*ar;
    }
}
template<int TM>
__device__ __forceinline__ void ry_reg(float (&re)[8], float (&im)[8],
                                       float c, float s) {
#pragma unroll
    for (int r = 0; r < 8; r++) {
        if (r & TM) continue;
        const int q = r | TM;
        float ar = re[r], ai = im[r], br = re[q], bi = im[q];
        re[r] = c*ar - s*br;  im[r] = c*ai - s*bi;
        re[q] = s*ar + c*br;  im[q] = s*ai + c*bi;
    }
}
// CNOT, target = register bit TM, control position CP (global bit index)
template<int TM, int CP>
__device__ __forceinline__ void cnot_rt(float (&re)[8], float (&im)[8], int lane) {
    if constexpr (CP >= 3) {
        bool cb = ((lane >> (CP - 3)) & 1) != 0;
#pragma unroll
        for (int r = 0; r < 8; r++) {
            if (r & TM) continue;
            const int q = r | TM;
            float ar = re[r], ai = im[r], br = re[q], bi = im[q];
            re[r] = cb ? br : ar;  im[r] = cb ? bi : ai;
            re[q] = cb ? ar : br;  im[q] = cb ? ai : bi;
        }
    } else {
        // control bit lives in r: compile-time swap (pure register rename)
#pragma unroll
        for (int r = 0; r < 8; r++) {
            if ((r & TM) == 0 && ((r >> CP) & 1)) {
                const int q = r | TM;
                float t;
                t = re[r]; re[r] = re[q]; re[q] = t;
                t = im[r]; im[r] = im[q]; im[q] = t;
            }
        }
    }
}
// CNOT, target = lane bit (xor mask M), control position CP
template<int M, int CP>
__device__ __forceinline__ void cnot_lt(float (&re)[8], float (&im)[8], int lane) {
    if constexpr (CP >= 3) {
        bool cb = ((lane >> (CP - 3)) & 1) != 0;
#pragma unroll
        for (int r = 0; r < 8; r++) {
            double d = __shfl_xor_sync(0xffffffffu, cpack(re[r], im[r]), M);
            float pr, pi; cunpack(d, pr, pi);
            re[r] = cb ? pr : re[r];
            im[r] = cb ? pi : im[r];
        }
    } else {
        // control bit lives in r: only half the registers move (compile-time)
#pragma unroll
        for (int r = 0; r < 8; r++) {
            if ((r >> CP) & 1) {
                double d = __shfl_xor_sync(0xffffffffu, cpack(re[r], im[r]), M);
                cunpack(d, re[r], im[r]);
            } else {
                // partner lanes still participate in this r's exchange
                __shfl_xor_sync(0xffffffffu, 0.f, M);
            }
        }
    }
}

// ---- compile-time gate dispatcher -----------------------------------------
template<int G>
__device__ __forceinline__ void do_gate(float (&re)[8], float (&im)[8],
                                        const float* __restrict__ gc,
                                        const float* __restrict__ gs, int lane) {
    if constexpr (G >= NOPS) {                       // final RY layer, wire G-20
        constexpr int p = 7 - (G - NOPS);
        const float c = gc[G], s = gs[G];
        if constexpr (p >= 3) ry_lane<(1 << (p - 3))>(re, im, c, s, lane);
        else                  ry_reg<(1 << p)>(re, im, c, s);
    } else {
        constexpr int kind = op_kind(G);
        constexpr int wa = op_a(G);
        constexpr int wb = op_b(G);
        if constexpr (kind == 3) {
            constexpr int cp = 7 - wa;
            constexpr int tp = 7 - wb;
            if constexpr (tp >= 3) cnot_lt<(1 << (tp - 3)), cp>(re, im, lane);
            else                   cnot_rt<(1 << tp), cp>(re, im, lane);
        } else if constexpr (kind == 2) {
            rz_g<7 - wa>(re, im, gc[G], gs[G], lane);
        } else if constexpr (kind == 0) {
            constexpr int p = 7 - wa;
            const float c = gc[G], s = gs[G];
            if constexpr (p >= 3) rx_lane<(1 << (p - 3))>(re, im, c, s);
            else                  rx_reg<(1 << p)>(re, im, c, s);
        } else {
            constexpr int p = 7 - wa;
            const float c = gc[G], s = gs[G];
            if constexpr (p >= 3) ry_lane<(1 << (p - 3))>(re, im, c, s, lane);
            else                  ry_reg<(1 << p)>(re, im, c, s);
        }
    }
}
template<int G>
__device__ __forceinline__ void run_gates(float (&re)[8], float (&im)[8],
                                          const float* __restrict__ gc,
                                          const float* __restrict__ gs, int lane) {
    if constexpr (G < 28) {
        do_gate<G>(re, im, gc, gs, lane);
        run_gates<G + 1>(re, im, gc, gs, lane);
    }
}

// ---------------- kernel 1: statevector sim + MLP layer 1 ------------------
__global__ __launch_bounds__(256)
void qsim_kernel(const float* __restrict__ x,
                 const float* __restrict__ ry_theta,
                 const float* __restrict__ rand_params,
                 const float* __restrict__ W1,
                 const float* __restrict__ b1)
{
    __shared__ float gc[28], gs[28];
    __shared__ float W1t[8 * 64];
    __shared__ float b1s[64];
    __shared__ float Hs[64][9];           // pad 9: conflict-free scatter

    const int tid = threadIdx.x;
    if (tid < 28) {
        float th = (tid < 20) ? rand_params[tid] : ry_theta[tid - 20];
        float s, c;
        sincosf(0.5f * th, &s, &c);
        gc[tid] = c;
        gs[tid] = s;                      // CNOT slots unused by do_gate
    }
    if (tid < 64) b1s[tid] = b1[tid];
    for (int i = tid; i < 512; i += 256) {
        int j = i >> 3, w = i & 7;
        W1t[w * 64 + j] = W1[i];          // transpose: conflict-free reads
    }
    __syncthreads();

    const int lane  = tid & 31;
    const int wid   = tid >> 5;
    const int token0 = blockIdx.x * 8;
    const int token  = token0 + wid;

    // ---- initial product state from the 8 input features ----
    const float* xf = x + (size_t)token * 512;
    float cw[8], sw[8];
#pragma unroll
    for (int w = 0; w < 8; w++) {
        float f = __ldg(xf + w);
        __sincosf(0.5f * f, &sw[w], &cw[w]);
    }
    float lf = 1.f;
#pragma unroll
    for (int w = 0; w < 5; w++)           // wires 0..4 live on lane bits 4..0
        lf *= ((lane >> (4 - w)) & 1) ? sw[w] : cw[w];
    float re[8], im[8];
#pragma unroll
    for (int r = 0; r < 8; r++) {
        float v = lf;
        v *= (r & 4) ? sw[5] : cw[5];
        v *= (r & 2) ? sw[6] : cw[6];
        v *= (r & 1) ? sw[7] : cw[7];
        re[r] = v; im[r] = 0.f;
    }

    // ---- 20 random gates + 8 final RY gates (fully unrolled) ----
    run_gates<0>(re, im, gc, gs, lane);

    // ---- probs -> 8 Z expectations (butterfly reductions) ----
    float S = 0.f, E5 = 0.f, E6 = 0.f, E7 = 0.f;
#pragma unroll
    for (int r = 0; r < 8; r++) {
        float p = re[r] * re[r] + im[r] * im[r];
        S  += p;
        E5 += (r & 4) ? -p : p;
        E6 += (r & 2) ? -p : p;
        E7 += (r & 1) ? -p : p;
    }
    float ev[8];
#pragma unroll
    for (int w = 0; w < 5; w++) {
        float v = ((lane >> (4 - w)) & 1) ? -S : S;
#pragma unroll
        for (int m = 16; m >= 1; m >>= 1) v += __shfl_xor_sync(0xffffffffu, v, m);
        ev[w] = v;
    }
    {
        float Ein[3] = {E5, E6, E7};
#pragma unroll
        for (int w = 5; w < 8; w++) {
            float v = Ein[w - 5];
#pragma unroll
            for (int m = 16; m >= 1; m >>= 1) v += __shfl_xor_sync(0xffffffffu, v, m);
            ev[w] = v;
        }
    }

    // ---- MLP layer 1: h = relu(ev @ W1^T + b1), staged to smem ----
#pragma unroll
    for (int half = 0; half < 2; half++) {
        const int j = lane + half * 32;
        float acc = b1s[j];
#pragma unroll
        for (int w = 0; w < 8; w++) acc = fmaf(ev[w], W1t[w * 64 + j], acc);
        Hs[j][wid] = fmaxf(acc, 0.f);
    }
    __syncthreads();

    // coalesced transposed writeout: g_Ht[j][token0+tok]
#pragma unroll
    for (int it = 0; it < 2; it++) {
        const int idx = it * 256 + tid;
        const int j = idx >> 3, tok = idx & 7;
        g_Ht[j * MAXTOK + token0 + tok] = Hs[j][tok];
    }
}

// ---------------- kernel 2: out = H @ W2^T + b2 ----------------------------
// M=16384, N=512, K=64.  BM=128, BN=64, 256 threads.
// Per thread: 8 m-rows x 4 n-cols; acc packed as m-pairs (fma.rn.f32x2).
// B staged in smem as pre-duplicated (v,v) 64-bit pairs -> zero pack MOVs.
__global__ __launch_bounds__(256)
void mlp2_kernel(const float* __restrict__ W2,
                 const float* __restrict__ b2,
                 float* __restrict__ out)
{
    extern __shared__ char dynsmem[];
    float* As = (float*)dynsmem;                                   // [64][128]
    unsigned long long* Bp = (unsigned long long*)(dynsmem + 64 * 128 * 4); // [64][64]

    const int tid = threadIdx.x;
    const int m0 = blockIdx.y * 128;
    const int n0 = blockIdx.x * 64;

    // load A tile: 64k x 128m (coalesced from transposed g_Ht)
#pragma unroll
    for (int it = 0; it < 8; it++) {
        const int c  = it * 256 + tid;
        const int k  = c >> 5;
        const int mq = c & 31;
        float4 v = *(const float4*)(g_Ht + (size_t)k * MAXTOK + m0 + mq * 4);
        *(float4*)&As[k * 128 + mq * 4] = v;
    }
    // load B tile as duplicated pairs: Bp[k][n] = (W2[n0+n][k], same)
#pragma unroll
    for (int it = 0; it < 4; it++) {
        const int c  = it * 256 + tid;
        const int n  = c & 63;
        const int kq = c >> 6;
        float4 v = *(const float4*)(W2 + (size_t)(n0 + n) * 64 + kq * 4);
        Bp[(kq * 4 + 0) * 64 + n] = pk2(v.x, v.x);
        Bp[(kq * 4 + 1) * 64 + n] = pk2(v.y, v.y);
        Bp[(kq * 4 + 2) * 64 + n] = pk2(v.z, v.z);
        Bp[(kq * 4 + 3) * 64 + n] = pk2(v.w, v.w);
    }
    __syncthreads();

    const int tx = tid & 15;     // n: cols {tx*2, tx*2+1, 32+tx*2, 33+tx*2}
    const int ty = tid >> 4;     // m: rows ty*4..+3 and 64+ty*4..+3

    unsigned long long acc[4][4];  // [m-pair][n-slot]
#pragma unroll
    for (int p = 0; p < 4; p++)
#pragma unroll
        for (int n = 0; n < 4; n++) acc[p][n] = 0ull;

#pragma unroll 16
    for (int k = 0; k < 64; k++) {
        ulonglong2 a01 = *(const ulonglong2*)&As[k * 128 + ty * 4];
        ulonglong2 a23 = *(const ulonglong2*)&As[k * 128 + 64 + ty * 4];
        unsigned long long ap[4] = {a01.x, a01.y, a23.x, a23.y};
        // phase-contiguous pair reads: lanes 0..15 cover 256B contiguous
        ulonglong2 b01 = *(const ulonglong2*)&Bp[k * 64 + tx * 2];
        ulonglong2 b23 = *(const ulonglong2*)&Bp[k * 64 + 32 + tx * 2];
        unsigned long long bp[4] = {b01.x, b01.y, b23.x, b23.y};
#pragma unroll
        for (int p = 0; p < 4; p++)
#pragma unroll
            for (int n = 0; n < 4; n++) fma2(acc[p][n], ap[p], bp[n]);
    }

    // n-column bases for the 4 slots
    const int c0 = n0 + tx * 2;          // slots 0,1 -> c0, c0+1
    const int c2 = n0 + 32 + tx * 2;     // slots 2,3 -> c2, c2+1
    const float2 bb01 = *(const float2*)(b2 + c0);
    const float2 bb23 = *(const float2*)(b2 + c2);
#pragma unroll
    for (int p = 0; p < 4; p++) {
        const int rlo = m0 + ((p & 2) ? 64 : 0) + ty * 4 + (p & 1) * 2;
        float l0, h0, l1, h1, l2, h2, l3, h3;
        unpk2(acc[p][0], l0, h0);
        unpk2(acc[p][1], l1, h1);
        unpk2(acc[p][2], l2, h2);
        unpk2(acc[p][3], l3, h3);
        float2 olo01 = {l0 + bb01.x, l1 + bb01.y};
        float2 ohi01 = {h0 + bb01.x, h1 + bb01.y};
        float2 olo23 = {l2 + bb23.x, l3 + bb23.y};
        float2 ohi23 = {h2 + bb23.x, h3 + bb23.y};
        *(float2*)(out + (size_t)rlo * 512 + c0)       = olo01;
        *(float2*)(out + (size_t)rlo * 512 + c2)       = olo23;
        *(float2*)(out + (size_t)(rlo + 1) * 512 + c0) = ohi01;
        *(float2*)(out + (size_t)(rlo + 1) * 512 + c2) = ohi23;
    }
}

// ---------------- entry point ----------------------------------------------
extern "C" void kernel_launch(void* const* d_in, const int* in_sizes, int n_in,
                              void* d_out, int out_size)
{
    const float* x  = (const float*)d_in[0];
    const float* ry = (const float*)d_in[1];
    const float* rp = (const float*)d_in[2];
    const float* W1 = (const float*)d_in[3];
    const float* b1 = (const float*)d_in[4];
    const float* W2 = (const float*)d_in[5];
    const float* b2 = (const float*)d_in[6];
    float* out = (float*)d_out;

    const int tokens = in_sizes[0] / 512;      // 16384

    qsim_kernel<<<tokens / 8, 256>>>(x, ry, rp, W1, b1);

    const int smem2 = 64 * 128 * 4 + 64 * 64 * 8;   // 65536 B
    cudaFuncSetAttribute(mlp2_kernel,
                         cudaFuncAttributeMaxDynamicSharedMemorySize, smem2);
    dim3 g2(512 / 64, tokens / 128);
    mlp2_kernel<<<g2, 256, smem2>>>(W2, b2, out);
}

// round 15
// speedup vs baseline: 1.8851x; 1.4224x over previous
#include <cuda_runtime.h>
#include <cuda_bf16.h>
#include <cstdint>

// ---------------------------------------------------------------------------
// QuantumFeedForwardBlock: 8-wire statevector sim (1 warp/token) + MLP GEMM
// Inputs (metadata order): x[4,4096,512] f32, ry_theta[8], rand_params[20],
//                          W1[64,8], b1[64], W2[512,64], b2[512]
// Output: f32 [4,4096,512]
// R13: mlp2 moved to tensor cores — split-bf16 (hi/lo) HMMA m16n8k16,
//      3 K-block products (hi*whi + lo*whi + hi*wlo), error ~1e-5.
//      qsim epilogue emits bf16 hi|lo activations directly.
// ---------------------------------------------------------------------------

#define NOPS 20
#define MAXTOK 16384

__device__ __nv_bfloat16 g_A[MAXTOK * 128];   // [m][0:64]=hi(h), [64:128]=lo(h)

struct Ops { int kind[NOPS]; int a[NOPS]; int b[NOPS]; };

// ---------------- constexpr numpy-legacy MT19937 ---------------------------
struct MTState { uint32_t mt[624]; int mti; };

__host__ __device__ constexpr void mt_seed(MTState& s, uint32_t seed) {
    s.mt[0] = seed;
    for (int i = 1; i < 624; i++)
        s.mt[i] = 1812433253u * (s.mt[i-1] ^ (s.mt[i-1] >> 30)) + (uint32_t)i;
    s.mti = 624;
}
__host__ __device__ constexpr uint32_t mt_next(MTState& s) {
    if (s.mti >= 624) {
        for (int i = 0; i < 624; i++) {
            uint32_t y = (s.mt[i] & 0x80000000u) | (s.mt[(i+1)%624] & 0x7fffffffu);
            uint32_t v = s.mt[(i+397)%624] ^ (y >> 1);
            if (y & 1u) v ^= 0x9908b0dfu;
            s.mt[i] = v;
        }
        s.mti = 0;
    }
    uint32_t y = s.mt[s.mti++];
    y ^= y >> 11;
    y ^= (y << 7)  & 0x9d2c5680u;
    y ^= (y << 15) & 0xefc60000u;
    y ^= y >> 18;
    return y;
}
__host__ __device__ constexpr uint32_t mt_bounded(MTState& s, uint32_t maxv) {
    uint32_t mask = maxv;
    mask |= mask >> 1; mask |= mask >> 2; mask |= mask >> 4;
    mask |= mask >> 8; mask |= mask >> 16;
    uint32_t v = mt_next(s) & mask;
    while (v > maxv) v = mt_next(s) & mask;
    return v;
}
__host__ __device__ constexpr Ops build_ops_ce() {
    Ops ops{};
    MTState st{};
    mt_seed(st, 0u);
    for (int i = 0; i < NOPS; i++) {
        uint32_t k = mt_bounded(st, 3u);               // randint(4)
        if (k == 3u) {                                  // cnot: choice(8,2,False)
            int perm[8] = {0,1,2,3,4,5,6,7};
            for (int ii = 7; ii >= 1; ii--) {           // legacy Fisher-Yates
                uint32_t j = mt_bounded(st, (uint32_t)ii);
                int t = perm[ii]; perm[ii] = perm[j]; perm[j] = t;
            }
            ops.kind[i] = 3; ops.a[i] = perm[0]; ops.b[i] = perm[1];
        } else {
            uint32_t w = mt_bounded(st, 7u);            // randint(8)
            ops.kind[i] = (int)k; ops.a[i] = (int)w; ops.b[i] = 0;
        }
    }
    return ops;
}
__host__ __device__ constexpr int op_kind(int g) { return build_ops_ce().kind[g]; }
__host__ __device__ constexpr int op_a(int g)    { return build_ops_ce().a[g]; }
__host__ __device__ constexpr int op_b(int g)    { return build_ops_ce().b[g]; }

// ---------------- device helpers -------------------------------------------
__device__ __forceinline__ double cpack(float r, float i) {
    return __hiloint2double(__float_as_int(i), __float_as_int(r));
}
__device__ __forceinline__ void cunpack(double d, float& r, float& i) {
    r = __int_as_float(__double2loint(d));
    i = __int_as_float(__double2hiint(d));
}
__device__ __forceinline__ uint32_t smem_u32(const void* p) {
    return (uint32_t)__cvta_generic_to_shared(p);
}
__device__ __forceinline__ void ldsm4(uint32_t* r, uint32_t addr) {
    asm volatile("ldmatrix.sync.aligned.m8n8.x4.shared.b16 {%0,%1,%2,%3}, [%4];"
        : "=r"(r[0]), "=r"(r[1]), "=r"(r[2]), "=r"(r[3]) : "r"(addr));
}
__device__ __forceinline__ void ldsm2(uint32_t* r, uint32_t addr) {
    asm volatile("ldmatrix.sync.aligned.m8n8.x2.shared.b16 {%0,%1}, [%2];"
        : "=r"(r[0]), "=r"(r[1]) : "r"(addr));
}
__device__ __forceinline__ void mma_bf16(float* c, const uint32_t* a,
                                         const uint32_t* b) {
    asm volatile(
        "mma.sync.aligned.m16n8k16.row.col.f32.bf16.bf16.f32 "
        "{%0,%1,%2,%3}, {%4,%5,%6,%7}, {%8,%9}, {%0,%1,%2,%3};"
        : "+f"(c[0]), "+f"(c[1]), "+f"(c[2]), "+f"(c[3])
        : "r"(a[0]), "r"(a[1]), "r"(a[2]), "r"(a[3]), "r"(b[0]), "r"(b[1]));
}

// ---- gate helpers, masks/positions as template parameters -----------------
template<int M>
__device__ __forceinline__ void rx_lane(float (&re)[8], float (&im)[8],
                                        float c, float s) {
#pragma unroll
    for (int r = 0; r < 8; r++) {
        double d = __shfl_xor_sync(0xffffffffu, cpack(re[r], im[r]), M);
        float pr, pi; cunpack(d, pr, pi);
        float nr = c * re[r] + s * pi;
        float ni = c * im[r] - s * pr;
        re[r] = nr; im[r] = ni;
    }
}
template<int M>
__device__ __forceinline__ void ry_lane(float (&re)[8], float (&im)[8],
                                        float c, float s, int lane) {
    float ss = (lane & M) ? s : -s;
#pragma unroll
    for (int r = 0; r < 8; r++) {
        double d = __shfl_xor_sync(0xffffffffu, cpack(re[r], im[r]), M);
        float pr, pi; cunpack(d, pr, pi);
        re[r] = c * re[r] + ss * pr;
        im[r] = c * im[r] + ss * pi;
    }
}
template<int P>
__device__ __forceinline__ void rz_g(float (&re)[8], float (&im)[8],
                                     float c, float s, int lane) {
    if constexpr (P >= 3) {
        float se = ((lane >> (P - 3)) & 1) ? s : -s;
#pragma unroll
        for (int r = 0; r < 8; r++) {
            float nr = c * re[r] - se * im[r];
            float ni = c * im[r] + se * re[r];
            re[r] = nr; im[r] = ni;
        }
    } else {
#pragma unroll
        for (int r = 0; r < 8; r++) {
            const float se = ((r >> P) & 1) ? s : -s;   // compile-time sign
            float nr = c * re[r] - se * im[r];
            float ni = c * im[r] + se * re[r];
            re[r] = nr; im[r] = ni;
        }
    }
}
template<int TM>
__device__ __forceinline__ void rx_reg(float (&re)[8], float (&im)[8],
                                       float c, float s) {
#pragma unroll
    for (int r = 0; r < 8; r++) {
        if (r & TM) continue;
        const int q = r | TM;
        float ar = re[r], ai = im[r], br = re[q], bi = im[q];
        re[r] = c*ar + s*bi;  im[r] = c*ai - s*br;
        re[q] = c*br + s*ai;  im[q] = c*bi - s*ar;
    }
}
template<int TM>
__device__ __forceinline__ void ry_reg(float (&re)[8], float (&im)[8],
                                       float c, float s) {
#pragma unroll
    for (int r = 0; r < 8; r++) {
        if (r & TM) continue;
        const int q = r | TM;
        float ar = re[r], ai = im[r], br = re[q], bi = im[q];
        re[r] = c*ar - s*br;  im[r] = c*ai - s*bi;
        re[q] = s*ar + c*br;  im[q] = s*ai + c*bi;
    }
}
template<int TM, int CP>
__device__ __forceinline__ void cnot_rt(float (&re)[8], float (&im)[8], int lane) {
    if constexpr (CP >= 3) {
        bool cb = ((lane >> (CP - 3)) & 1) != 0;
#pragma unroll
        for (int r = 0; r < 8; r++) {
            if (r & TM) continue;
            const int q = r | TM;
            float ar = re[r], ai = im[r], br = re[q], bi = im[q];
            re[r] = cb ? br : ar;  im[r] = cb ? bi : ai;
            re[q] = cb ? ar : br;  im[q] = cb ? ai : bi;
        }
    } else {
#pragma unroll
        for (int r = 0; r < 8; r++) {
            if ((r & TM) == 0 && ((r >> CP) & 1)) {
                const int q = r | TM;
                float t;
                t = re[r]; re[r] = re[q]; re[q] = t;
                t = im[r]; im[r] = im[q]; im[q] = t;
            }
        }
    }
}
template<int M, int CP>
__device__ __forceinline__ void cnot_lt(float (&re)[8], float (&im)[8], int lane) {
    if constexpr (CP >= 3) {
        bool cb = ((lane >> (CP - 3)) & 1) != 0;
#pragma unroll
        for (int r = 0; r < 8; r++) {
            double d = __shfl_xor_sync(0xffffffffu, cpack(re[r], im[r]), M);
            float pr, pi; cunpack(d, pr, pi);
            re[r] = cb ? pr : re[r];
            im[r] = cb ? pi : im[r];
        }
    } else {
#pragma unroll
        for (int r = 0; r < 8; r++) {
            if ((r >> CP) & 1) {
                double d = __shfl_xor_sync(0xffffffffu, cpack(re[r], im[r]), M);
                cunpack(d, re[r], im[r]);
            } else {
                __shfl_xor_sync(0xffffffffu, 0.f, M);
            }
        }
    }
}

// ---- compile-time gate dispatcher -----------------------------------------
template<int G>
__device__ __forceinline__ void do_gate(float (&re)[8], float (&im)[8],
                                        const float* __restrict__ gc,
                                        const float* __restrict__ gs, int lane) {
    if constexpr (G >= NOPS) {                       // final RY layer, wire G-20
        constexpr int p = 7 - (G - NOPS);
        const float c = gc[G], s = gs[G];
        if constexpr (p >= 3) ry_lane<(1 << (p - 3))>(re, im, c, s, lane);
        else                  ry_reg<(1 << p)>(re, im, c, s);
    } else {
        constexpr int kind = op_kind(G);
        constexpr int wa = op_a(G);
        constexpr int wb = op_b(G);
        if constexpr (kind == 3) {
            constexpr int cp = 7 - wa;
            constexpr int tp = 7 - wb;
            if constexpr (tp >= 3) cnot_lt<(1 << (tp - 3)), cp>(re, im, lane);
            else                   cnot_rt<(1 << tp), cp>(re, im, lane);
        } else if constexpr (kind == 2) {
            rz_g<7 - wa>(re, im, gc[G], gs[G], lane);
        } else if constexpr (kind == 0) {
            constexpr int p = 7 - wa;
            const float c = gc[G], s = gs[G];
            if constexpr (p >= 3) rx_lane<(1 << (p - 3))>(re, im, c, s);
            else                  rx_reg<(1 << p)>(re, im, c, s);
        } else {
            constexpr int p = 7 - wa;
            const float c = gc[G], s = gs[G];
            if constexpr (p >= 3) ry_lane<(1 << (p - 3))>(re, im, c, s, lane);
            else                  ry_reg<(1 << p)>(re, im, c, s);
        }
    }
}
template<int G>
__device__ __forceinline__ void run_gates(float (&re)[8], float (&im)[8],
                                          const float* __restrict__ gc,
                                          const float* __restrict__ gs, int lane) {
    if constexpr (G < 28) {
        do_gate<G>(re, im, gc, gs, lane);
        run_gates<G + 1>(re, im, gc, gs, lane);
    }
}

// ---------------- kernel 1: statevector sim + MLP layer 1 ------------------
__global__ __launch_bounds__(256)
void qsim_kernel(const float* __restrict__ x,
                 const float* __restrict__ ry_theta,
                 const float* __restrict__ rand_params,
                 const float* __restrict__ W1,
                 const float* __restrict__ b1)
{
    __shared__ float gc[28], gs[28];
    __shared__ float W1t[8 * 64];
    __shared__ float b1s[64];
    __shared__ float Hs[64][9];           // pad 9: conflict-free scatter

    const int tid = threadIdx.x;
    if (tid < 28) {
        float th = (tid < 20) ? rand_params[tid] : ry_theta[tid - 20];
        float s, c;
        sincosf(0.5f * th, &s, &c);
        gc[tid] = c;
        gs[tid] = s;                      // CNOT slots unused by do_gate
    }
    if (tid < 64) b1s[tid] = b1[tid];
    for (int i = tid; i < 512; i += 256) {
        int j = i >> 3, w = i & 7;
        W1t[w * 64 + j] = W1[i];
    }
    __syncthreads();

    const int lane  = tid & 31;
    const int wid   = tid >> 5;
    const int token0 = blockIdx.x * 8;
    const int token  = token0 + wid;

    // ---- initial product state from the 8 input features ----
    const float* xf = x + (size_t)token * 512;
    float cw[8], sw[8];
#pragma unroll
    for (int w = 0; w < 8; w++) {
        float f = __ldg(xf + w);
        __sincosf(0.5f * f, &sw[w], &cw[w]);
    }
    float lf = 1.f;
#pragma unroll
    for (int w = 0; w < 5; w++)           // wires 0..4 live on lane bits 4..0
        lf *= ((lane >> (4 - w)) & 1) ? sw[w] : cw[w];
    float re[8], im[8];
#pragma unroll
    for (int r = 0; r < 8; r++) {
        float v = lf;
        v *= (r & 4) ? sw[5] : cw[5];
        v *= (r & 2) ? sw[6] : cw[6];
        v *= (r & 1) ? sw[7] : cw[7];
        re[r] = v; im[r] = 0.f;
    }

    // ---- 20 random gates + 8 final RY gates (fully unrolled) ----
    run_gates<0>(re, im, gc, gs, lane);

    // ---- probs -> 8 Z expectations (butterfly reductions) ----
    float S = 0.f, E5 = 0.f, E6 = 0.f, E7 = 0.f;
#pragma unroll
    for (int r = 0; r < 8; r++) {
        float p = re[r] * re[r] + im[r] * im[r];
        S  += p;
        E5 += (r & 4) ? -p : p;
        E6 += (r & 2) ? -p : p;
        E7 += (r & 1) ? -p : p;
    }
    float ev[8];
#pragma unroll
    for (int w = 0; w < 5; w++) {
        float v = ((lane >> (4 - w)) & 1) ? -S : S;
#pragma unroll
        for (int m = 16; m >= 1; m >>= 1) v += __shfl_xor_sync(0xffffffffu, v, m);
        ev[w] = v;
    }
    {
        float Ein[3] = {E5, E6, E7};
#pragma unroll
        for (int w = 5; w < 8; w++) {
            float v = Ein[w - 5];
#pragma unroll
            for (int m = 16; m >= 1; m >>= 1) v += __shfl_xor_sync(0xffffffffu, v, m);
            ev[w] = v;
        }
    }

    // ---- MLP layer 1: h = relu(ev @ W1^T + b1), staged to smem ----
#pragma unroll
    for (int half = 0; half < 2; half++) {
        const int j = lane + half * 32;
        float acc = b1s[j];
#pragma unroll
        for (int w = 0; w < 8; w++) acc = fmaf(ev[w], W1t[w * 64 + j], acc);
        Hs[j][wid] = fmaxf(acc, 0.f);
    }
    __syncthreads();

    // ---- bf16 hi/lo split writeout: g_A[m][0:64]=hi, [64:128]=lo ----
#pragma unroll
    for (int it = 0; it < 2; it++) {
        const int idx = it * 256 + tid;           // 512 h-values per block
        const int tok = idx >> 6, j = idx & 63;
        float h = Hs[j][tok];
        __nv_bfloat16 hi = __float2bfloat16(h);
        __nv_bfloat16 lo = __float2bfloat16(h - __bfloat162float(hi));
        __nv_bfloat16* row = g_A + (size_t)(token0 + tok) * 128;
        row[j]      = hi;
        row[64 + j] = lo;
    }
}

// ---------------- kernel 2: out = H @ W2^T + b2  (split-bf16 HMMA) ---------
// M=16384, N=512, K=64 fp32 ->  bf16 hi/lo, 3 K-block products:
//   blk0: A=hi, B=whi   blk1: A=lo, B=whi   blk2: A=hi, B=wlo
// BM=128, BN=64, 256 threads (8 warps as 4m x 2n, each warp 32m x 32n).
#define PITCH 272   // smem row pitch in bytes (136 bf16): conflict-free ldmatrix
__global__ __launch_bounds__(256)
void mlp2_kernel(const float* __restrict__ W2,
                 const float* __restrict__ b2,
                 float* __restrict__ out)
{
    extern __shared__ char smem[];
    char* As = smem;                  // [128 rows][PITCH]  bf16 (hi|lo)
    char* Bs = smem + 128 * PITCH;    // [64 rows][PITCH]   bf16 (whi|wlo)

    const int tid = threadIdx.x;
    const int m0 = blockIdx.y * 128;
    const int n0 = blockIdx.x * 64;

    // ---- load A tile (bf16, 128 rows x 256B) ----
#pragma unroll
    for (int it = 0; it < 8; it++) {
        const int c = it * 256 + tid;             // 2048 x 16B chunks
        const int row = c >> 4, ch = c & 15;
        uint4 v = *(const uint4*)((const char*)g_A + (size_t)(m0 + row) * 256 + ch * 16);
        *(uint4*)(As + row * PITCH + ch * 16) = v;
    }
    // ---- load W2 tile (f32) and split to bf16 hi|lo in smem ----
#pragma unroll
    for (int it = 0; it < 8; it++) {
        const int c = it * 256 + tid;             // 2048 x float2
        const int n = c >> 5, kk = c & 31;        // k pair index
        float2 v = *(const float2*)(W2 + (size_t)(n0 + n) * 64 + kk * 2);
        __nv_bfloat16 h0 = __float2bfloat16(v.x);
        __nv_bfloat16 h1 = __float2bfloat16(v.y);
        __nv_bfloat16 l0 = __float2bfloat16(v.x - __bfloat162float(h0));
        __nv_bfloat16 l1 = __float2bfloat16(v.y - __bfloat162float(h1));
        *(__nv_bfloat162*)(Bs + n * PITCH + kk * 4)       = __nv_bfloat162(h0, h1);
        *(__nv_bfloat162*)(Bs + n * PITCH + 128 + kk * 4) = __nv_bfloat162(l0, l1);
    }
    __syncthreads();

    const int lane = tid & 31;
    const int wid  = tid >> 5;
    const int wm = (wid & 3) * 32;    // warp m-origin within tile
    const int wn = (wid >> 2) * 32;   // warp n-origin within tile

    const uint32_t aBase = smem_u32(As);
    const uint32_t bBase = smem_u32(Bs);
    // per-thread ldmatrix row offsets (bytes), k added per step
    uint32_t aRow[2], bRow[4];
#pragma unroll
    for (int mt = 0; mt < 2; mt++)
        aRow[mt] = aBase + (wm + mt * 16 + (lane & 15)) * PITCH + (lane >> 4) * 16;
#pragma unroll
    for (int nt = 0; nt < 4; nt++)
        bRow[nt] = bBase + (wn + nt * 8 + (lane & 7)) * PITCH + ((lane >> 3) & 1) * 16;

    float acc[2][4][4];
#pragma unroll
    for (int mt = 0; mt < 2; mt++)
#pragma unroll
        for (int nt = 0; nt < 4; nt++)
#pragma unroll
            for (int i = 0; i < 4; i++) acc[mt][nt][i] = 0.f;

#pragma unroll
    for (int blk = 0; blk < 3; blk++) {
        const int ka = (blk == 1) ? 128 : 0;      // A byte offset: hi,lo,hi
        const int kb = (blk == 2) ? 128 : 0;      // B byte offset: whi,whi,wlo
#pragma unroll
        for (int ks = 0; ks < 4; ks++) {
            const int koa = ka + ks * 32;          // 16 bf16 = 32 bytes
            const int kob = kb + ks * 32;
            uint32_t a[2][4], b[4][2];
#pragma unroll
            for (int mt = 0; mt < 2; mt++) ldsm4(a[mt], aRow[mt] + koa);
#pragma unroll
            for (int nt = 0; nt < 4; nt++) ldsm2(b[nt], bRow[nt] + kob);
#pragma unroll
            for (int mt = 0; mt < 2; mt++)
#pragma unroll
                for (int nt = 0; nt < 4; nt++)
                    mma_bf16(acc[mt][nt], a[mt], b[nt]);
        }
    }

    // ---- epilogue: add bias, write fp32 ----
#pragma unroll
    for (int nt = 0; nt < 4; nt++) {
        const int n = n0 + wn + nt * 8 + (lane & 3) * 2;
        const float2 bb = *(const float2*)(b2 + n);
#pragma unroll
        for (int mt = 0; mt < 2; mt++) {
            const int r0 = m0 + wm + mt * 16 + (lane >> 2);
            const float* c = acc[mt][nt];
            float2 o0 = {c[0] + bb.x, c[1] + bb.y};
            float2 o1 = {c[2] + bb.x, c[3] + bb.y};
            *(float2*)(out + (size_t)r0 * 512 + n)       = o0;
            *(float2*)(out + (size_t)(r0 + 8) * 512 + n) = o1;
        }
    }
}

// ---------------- entry point ----------------------------------------------
extern "C" void kernel_launch(void* const* d_in, const int* in_sizes, int n_in,
                              void* d_out, int out_size)
{
    const float* x  = (const float*)d_in[0];
    const float* ry = (const float*)d_in[1];
    const float* rp = (const float*)d_in[2];
    const float* W1 = (const float*)d_in[3];
    const float* b1 = (const float*)d_in[4];
    const float* W2 = (const float*)d_in[5];
    const float* b2 = (const float*)d_in[6];
    float* out = (float*)d_out;

    const int tokens = in_sizes[0] / 512;      // 16384

    qsim_kernel<<<tokens / 8, 256>>>(x, ry, rp, W1, b1);

    const int smem2 = (128 + 64) * PITCH;      // 52224 B
    cudaFuncSetAttribute(mlp2_kernel,
                         cudaFuncAttributeMaxDynamicSharedMemorySize, smem2);
    dim3 g2(512 / 64, tokens / 128);
    mlp2_kernel<<<g2, 256, smem2>>>(W2, b2, out);
}